// round 9
// baseline (speedup 1.0000x reference)
#include <cuda_runtime.h>
#include <cuda_bf16.h>
#include <mma.h>
#include <math.h>
#include <stdint.h>

using namespace nvcuda;

// ---------------- scratch (device globals; no allocations) ----------------
#define MAXN 76800
#define MAXE 768000
#define MAXNF (76800u * 216u)
#define MOLN 10240
#define MOLE 40960
#define MOLNF (10240u * 312u)

// protein-branch buffers
__device__ float g_Y[MAXNF];
__device__ float g_A[MAXNF];
__device__ float g_B[MAXNF];
__device__ float g_nrm[MAXN];
__device__ int   g_deg[MAXN];
__device__ int   g_cur[MAXN];
__device__ int   g_rowptr[MAXN + 1];
__device__ int   g_csr[MAXE];
__device__ int   g_bsum[128];
__device__ int   g_gcnt[256];
__device__ int   g_gptr[257];
__device__ float g_pool[256 * 312];
__device__ float g_fc1[256 * 1024];
__device__ __align__(16) __nv_bfloat16 g_Ab[76800u * 384u];
__device__ __align__(16) __nv_bfloat16 g_Wb2[128 * 192];
__device__ __align__(16) __nv_bfloat16 g_Wb3[256 * 384];
// molecule-branch buffers (private, for stream overlap)
__device__ float m_Y[MOLNF];
__device__ float m_A[MOLNF];
__device__ float m_B[MOLNF];
__device__ float m_nrm[MOLN];
__device__ int   m_deg[MOLN];
__device__ int   m_cur[MOLN];
__device__ int   m_rowptr[MOLN + 1];
__device__ int   m_csr[MOLE];
__device__ int   m_bsum[128];
__device__ int   m_gcnt[256];
__device__ int   m_gptr[257];
__device__ float m_pool[256 * 312];
__device__ float m_fc1[256 * 1024];
// shared tail
__device__ float g_cat[256 * 256];
__device__ float g_head[256 * 512];

static inline int gdiv(int n, int d) { return (n + d - 1) / d; }
static inline int pad64(int x) { return (x + 63) & ~63; }
static inline int pad128i(int x) { return (x + 127) & ~127; }

// ---------------- small utility kernels ----------------
__global__ void k_zero2i(int* a, int* b, int n) {
    int i = blockIdx.x * blockDim.x + threadIdx.x;
    if (i < n) { a[i] = 0; b[i] = 0; }
}

__global__ void k_zeroi(int* a, int n) {
    int i = blockIdx.x * blockDim.x + threadIdx.x;
    if (i < n) a[i] = 0;
}

__global__ void k_hist(const int* __restrict__ idx, int* __restrict__ acc, int n) {
    int i = blockIdx.x * blockDim.x + threadIdx.x;
    if (i < n) atomicAdd(&acc[idx[i]], 1);
}

__global__ void k_nrm(const int* __restrict__ deg, float* __restrict__ nrm, int n) {
    int i = blockIdx.x * blockDim.x + threadIdx.x;
    if (i < n) nrm[i] = rsqrtf((float)deg[i] + 1.f);
}

// ---- multi-block exclusive scan ----
__global__ void k_scan_blk(const int* __restrict__ in, int* __restrict__ out,
                           int* __restrict__ bsum, int n) {
    __shared__ int wsum[32];
    int tid = threadIdx.x;
    int lane = tid & 31, wid = tid >> 5;
    int i = blockIdx.x * 1024 + tid;
    int v = (i < n) ? in[i] : 0;
    int s = v;
#pragma unroll
    for (int off = 1; off < 32; off <<= 1) {
        int t = __shfl_up_sync(0xffffffffu, s, off);
        if (lane >= off) s += t;
    }
    if (lane == 31) wsum[wid] = s;
    __syncthreads();
    if (wid == 0) {
        int ws = wsum[lane];
#pragma unroll
        for (int off = 1; off < 32; off <<= 1) {
            int t = __shfl_up_sync(0xffffffffu, ws, off);
            if (lane >= off) ws += t;
        }
        wsum[lane] = ws;
    }
    __syncthreads();
    int wofs = (wid > 0) ? wsum[wid - 1] : 0;
    int incl = wofs + s;
    if (i < n) out[i] = incl - v;
    if (tid == 1023) bsum[blockIdx.x] = incl;
}

__global__ void k_scan_small(int* __restrict__ b, int nb) {
    __shared__ int wsum[4];
    int tid = threadIdx.x;
    int lane = tid & 31, wid = tid >> 5;
    int v = (tid < nb) ? b[tid] : 0;
    int s = v;
#pragma unroll
    for (int off = 1; off < 32; off <<= 1) {
        int t = __shfl_up_sync(0xffffffffu, s, off);
        if (lane >= off) s += t;
    }
    if (lane == 31) wsum[wid] = s;
    __syncthreads();
    if (tid == 0) {
        int c = 0;
        for (int w = 0; w < 4; w++) { int t = wsum[w]; wsum[w] = c; c += t; }
    }
    __syncthreads();
    int excl = wsum[wid] + s - v;
    __syncthreads();
    if (tid < nb) b[tid] = excl;
    if (tid == nb - 1) b[nb] = excl + v;
}

__global__ void k_scan_add(int* __restrict__ out, const int* __restrict__ bsum,
                           int n, int nb) {
    int i = blockIdx.x * blockDim.x + threadIdx.x;
    if (i < n) out[i] += bsum[i >> 10];
    if (i == 0) out[n] = bsum[nb];
}

__global__ void k_scan_ex(const int* __restrict__ in, int* __restrict__ out, int n) {
    __shared__ int wsum[32];
    __shared__ int carry_s;
    int tid = threadIdx.x;
    int lane = tid & 31, wid = tid >> 5;
    if (tid == 0) carry_s = 0;
    __syncthreads();
    for (int base = 0; base < n; base += 1024) {
        int i = base + tid;
        int v = (i < n) ? in[i] : 0;
        int s = v;
#pragma unroll
        for (int off = 1; off < 32; off <<= 1) {
            int t = __shfl_up_sync(0xffffffffu, s, off);
            if (lane >= off) s += t;
        }
        if (lane == 31) wsum[wid] = s;
        __syncthreads();
        if (wid == 0) {
            int ws = wsum[lane];
#pragma unroll
            for (int off = 1; off < 32; off <<= 1) {
                int t = __shfl_up_sync(0xffffffffu, ws, off);
                if (lane >= off) ws += t;
            }
            wsum[lane] = ws;
        }
        __syncthreads();
        int wofs = (wid > 0) ? wsum[wid - 1] : 0;
        int incl = carry_s + wofs + s;
        if (i < n) out[i] = incl - v;
        __syncthreads();
        if (tid == 1023) carry_s = incl;
        __syncthreads();
    }
    if (threadIdx.x == 0) out[n] = carry_s;
}

__global__ void k_fill(const int* __restrict__ src, const int* __restrict__ dst,
                       const int* __restrict__ rowptr, int* __restrict__ cur,
                       int* __restrict__ csr, int E) {
    int e = blockIdx.x * blockDim.x + threadIdx.x;
    if (e >= E) return;
    int d = dst[e];
    int p = rowptr[d] + atomicAdd(&cur[d], 1);
    csr[p] = src[e];
}

// ---------------- aggregation (fp32 out) ----------------
template <int NF>
__global__ void k_agg(const float* __restrict__ x, const float* __restrict__ nrm,
                      const int* __restrict__ rowptr, const int* __restrict__ csr,
                      float* __restrict__ y, int N, int F,
                      const float* __restrict__ bias, int dorelu) {
    int warp = (blockIdx.x * blockDim.x + threadIdx.x) >> 5;
    int lane = threadIdx.x & 31;
    if (warp >= N) return;
    int beg = rowptr[warp], end = rowptr[warp + 1];
    float ni = nrm[warp];

    float acc[NF];
#pragma unroll
    for (int j = 0; j < NF; j++) acc[j] = 0.f;

    int e = beg;
    for (; e + 1 < end; e += 2) {
        int s0 = csr[e], s1 = csr[e + 1];
        float n0 = nrm[s0], n1 = nrm[s1];
        const float* x0 = x + (size_t)s0 * F;
        const float* x1 = x + (size_t)s1 * F;
#pragma unroll
        for (int j = 0; j < NF; j++) {
            int f = lane + 32 * j;
            if (f < F) acc[j] += x0[f] * n0 + x1[f] * n1;
        }
    }
    if (e < end) {
        int s0 = csr[e];
        float n0 = nrm[s0];
        const float* x0 = x + (size_t)s0 * F;
#pragma unroll
        for (int j = 0; j < NF; j++) {
            int f = lane + 32 * j;
            if (f < F) acc[j] += x0[f] * n0;
        }
    }
    const float* xi = x + (size_t)warp * F;
    float* yi = y + (size_t)warp * F;
#pragma unroll
    for (int j = 0; j < NF; j++) {
        int f = lane + 32 * j;
        if (f < F) {
            float v = ni * (acc[j] + ni * xi[f]);
            if (bias) v += bias[f];
            if (dorelu) v = fmaxf(v, 0.f);
            yi[f] = v;
        }
    }
}

static void launch_agg(const float* x, const float* nrm, const int* rp, const int* csr,
                       float* y, int N, int F, const float* bias, int dorelu,
                       cudaStream_t st) {
    int blocks = gdiv(N, 8);
    int nf = gdiv(F, 32);
    switch (nf) {
        case 2: k_agg<2><<<blocks, 256, 0, st>>>(x, nrm, rp, csr, y, N, F, bias, dorelu); break;
        case 3: k_agg<3><<<blocks, 256, 0, st>>>(x, nrm, rp, csr, y, N, F, bias, dorelu); break;
        case 4: k_agg<4><<<blocks, 256, 0, st>>>(x, nrm, rp, csr, y, N, F, bias, dorelu); break;
        case 5: k_agg<5><<<blocks, 256, 0, st>>>(x, nrm, rp, csr, y, N, F, bias, dorelu); break;
        default: k_agg<8><<<blocks, 256, 0, st>>>(x, nrm, rp, csr, y, N, F, bias, dorelu); break;
    }
}

// ---------------- aggregation with K-packed split-bf16 output ----------------
// A'[row] = [Ah(Kp) | Ah(Kp) | Al(Kp)], zero-padded per section.
__device__ __forceinline__ void bf_split(float v, __nv_bfloat16& h, __nv_bfloat16& l) {
    h = __float2bfloat16_rn(v);
    l = __float2bfloat16_rn(v - __bfloat162float(h));
}

template <int NF>
__global__ void k_aggb(const float* __restrict__ x, const float* __restrict__ nrm,
                       const int* __restrict__ rowptr, const int* __restrict__ csr,
                       __nv_bfloat16* __restrict__ Ap, int N, int F, int Kp) {
    int warp = (blockIdx.x * blockDim.x + threadIdx.x) >> 5;
    int lane = threadIdx.x & 31;
    if (warp >= N) return;
    int beg = rowptr[warp], end = rowptr[warp + 1];
    float ni = nrm[warp];

    float acc[NF];
#pragma unroll
    for (int j = 0; j < NF; j++) acc[j] = 0.f;

    int e = beg;
    for (; e + 1 < end; e += 2) {
        int s0 = csr[e], s1 = csr[e + 1];
        float n0 = nrm[s0], n1 = nrm[s1];
        const float* x0 = x + (size_t)s0 * F;
        const float* x1 = x + (size_t)s1 * F;
#pragma unroll
        for (int j = 0; j < NF; j++) {
            int f = lane + 32 * j;
            if (f < F) acc[j] += x0[f] * n0 + x1[f] * n1;
        }
    }
    if (e < end) {
        int s0 = csr[e];
        float n0 = nrm[s0];
        const float* x0 = x + (size_t)s0 * F;
#pragma unroll
        for (int j = 0; j < NF; j++) {
            int f = lane + 32 * j;
            if (f < F) acc[j] += x0[f] * n0;
        }
    }
    const float* xi = x + (size_t)warp * F;
    __nv_bfloat16* ap = Ap + (size_t)warp * (3 * Kp);
#pragma unroll
    for (int j = 0; j < NF; j++) {
        int f = lane + 32 * j;
        if (f < F) {
            float v = ni * (acc[j] + ni * xi[f]);
            __nv_bfloat16 h, l;
            bf_split(v, h, l);
            ap[f] = h; ap[Kp + f] = h; ap[2 * Kp + f] = l;
        }
    }
    __nv_bfloat16 z = __float2bfloat16_rn(0.f);
    for (int f = F + lane; f < Kp; f += 32) {
        ap[f] = z; ap[Kp + f] = z; ap[2 * Kp + f] = z;
    }
}

static void launch_aggb(const float* x, const float* nrm, const int* rp, const int* csr,
                        __nv_bfloat16* Ap, int N, int F, int Kp, cudaStream_t st) {
    int blocks = gdiv(N, 8);
    int nf = gdiv(F, 32);
    switch (nf) {
        case 2: k_aggb<2><<<blocks, 256, 0, st>>>(x, nrm, rp, csr, Ap, N, F, Kp); break;
        case 3: k_aggb<3><<<blocks, 256, 0, st>>>(x, nrm, rp, csr, Ap, N, F, Kp); break;
        case 4: k_aggb<4><<<blocks, 256, 0, st>>>(x, nrm, rp, csr, Ap, N, F, Kp); break;
        default: k_aggb<5><<<blocks, 256, 0, st>>>(x, nrm, rp, csr, Ap, N, F, Kp); break;
    }
}

// ---------------- weight pack: Bp[n] = [Bh(Kp) | Bl(Kp) | Bh(Kp)] (n-major) ----
__global__ void k_cvtWpack(const float* __restrict__ W, __nv_bfloat16* __restrict__ Bp,
                           int K, int Mout, int Kp, int Mp) {
    int idx = blockIdx.x * blockDim.x + threadIdx.x;
    if (idx >= Mp * Kp) return;
    int n = idx / Kp, f = idx - n * Kp;
    float v = (f < K && n < Mout) ? W[(size_t)f * Mout + n] : 0.f;
    __nv_bfloat16 h, l;
    bf_split(v, h, l);
    size_t b = (size_t)n * (3 * Kp);
    Bp[b + f] = h; Bp[b + Kp + f] = l; Bp[b + 2 * Kp + f] = h;
}

// ---------------- bf16 wmma GEMM: C[Nr,Mout] = Ap[Nr,K3] @ Bp[Mp,K3]^T ----------
// Block 128x128, BK=64, 2-stage cp.async. 8 warps = 2(m) x 4(n), warp tile 64x32.
// Nr % 128 == 0, K3 % 64 == 0, Mp % 128 == 0; guards only on output columns.
#define WG_SMEM 81920

__global__ __launch_bounds__(256) void k_wgemm(
    const __nv_bfloat16* __restrict__ Ap, const __nv_bfloat16* __restrict__ Bp,
    const float* __restrict__ bias, float* __restrict__ C,
    int K3, int nst, int Mout, int ldc, int relu)
{
    extern __shared__ __align__(128) char dsm[];
    int tid = threadIdx.x;
    int wid = tid >> 5, lane = tid & 31;
    int warp_m = wid >> 2, warp_n = wid & 3;
    int row0 = blockIdx.y * 128, col0 = blockIdx.x * 128;
    uint32_t sbase = (uint32_t)__cvta_generic_to_shared(dsm);

    wmma::fragment<wmma::accumulator, 16, 16, 16, float> acc[4][2];
#pragma unroll
    for (int i = 0; i < 4; i++)
#pragma unroll
        for (int j = 0; j < 2; j++) wmma::fill_fragment(acc[i][j], 0.f);

    auto issue = [&](int t) {
        int buf = t & 1;
        int kbase = t * 64;
        uint32_t sA = sbase + (uint32_t)buf * 40960u;
        uint32_t sB = sA + 20480u;
#pragma unroll
        for (int u = 0; u < 4; u++) {
            int c = tid + 256 * u;
            int row = c >> 3;
            int ko = (c & 7) * 8;
            const void* ga = Ap + (size_t)(row0 + row) * K3 + kbase + ko;
            asm volatile("cp.async.cg.shared.global [%0], [%1], 16;"
                         :: "r"(sA + (uint32_t)(row * 160 + (c & 7) * 16)), "l"(ga));
            const void* gb = Bp + (size_t)(col0 + row) * K3 + kbase + ko;
            asm volatile("cp.async.cg.shared.global [%0], [%1], 16;"
                         :: "r"(sB + (uint32_t)(row * 160 + (c & 7) * 16)), "l"(gb));
        }
        asm volatile("cp.async.commit_group;");
    };

    issue(0);
    if (nst > 1) issue(1);

    for (int t = 0; t < nst; t++) {
        if (t + 1 < nst) asm volatile("cp.async.wait_group 1;");
        else             asm volatile("cp.async.wait_group 0;");
        __syncthreads();
        const __nv_bfloat16* pA = (const __nv_bfloat16*)(dsm + (t & 1) * 40960);
        const __nv_bfloat16* pB = (const __nv_bfloat16*)(dsm + (t & 1) * 40960 + 20480);
#pragma unroll
        for (int ks = 0; ks < 4; ks++) {
            wmma::fragment<wmma::matrix_b, 16, 16, 16, __nv_bfloat16, wmma::col_major> bfr[2];
#pragma unroll
            for (int j = 0; j < 2; j++)
                wmma::load_matrix_sync(bfr[j], pB + (warp_n * 32 + j * 16) * 80 + ks * 16, 80);
#pragma unroll
            for (int i = 0; i < 4; i++) {
                wmma::fragment<wmma::matrix_a, 16, 16, 16, __nv_bfloat16, wmma::row_major> afr;
                wmma::load_matrix_sync(afr, pA + (warp_m * 64 + i * 16) * 80 + ks * 16, 80);
#pragma unroll
                for (int j = 0; j < 2; j++)
                    wmma::mma_sync(acc[i][j], afr, bfr[j], acc[i][j]);
            }
        }
        __syncthreads();
        if (t + 2 < nst) issue(t + 2);
    }

    // epilogue: stage 16x16 tiles through smem, apply bias/relu, guard cols
    float* stg = (float*)(dsm + wid * 1024);
    int lr = lane >> 1;
    int lc = (lane & 1) * 8;
#pragma unroll
    for (int i = 0; i < 4; i++) {
        int r0 = row0 + warp_m * 64 + i * 16;
#pragma unroll
        for (int j = 0; j < 2; j++) {
            int c0 = col0 + warp_n * 32 + j * 16;
            wmma::store_matrix_sync(stg, acc[i][j], 16, wmma::mem_row_major);
            __syncwarp();
            float* Cr = C + (size_t)(r0 + lr) * ldc;
#pragma unroll
            for (int q = 0; q < 8; q++) {
                int c = c0 + lc + q;
                if (c < Mout) {
                    float v = stg[lr * 16 + lc + q] + bias[c];
                    if (relu) v = fmaxf(v, 0.f);
                    Cr[c] = v;
                }
            }
            __syncwarp();
        }
    }
}

static void launch_wg(const __nv_bfloat16* Ap, const __nv_bfloat16* Wp,
                      const float* bias, float* C,
                      int Nr, int Kp, int Mp, int Mout, int ldc, int relu,
                      cudaStream_t st) {
    int K3 = 3 * Kp;
    dim3 grid(Mp / 128, Nr / 128);
    k_wgemm<<<grid, 256, WG_SMEM, st>>>(Ap, Wp, bias, C, K3, K3 / 64, Mout, ldc, relu);
}

// ---------------- mean pool ----------------
__global__ void k_pool(const float* __restrict__ x, const int* __restrict__ gptr,
                       float* __restrict__ pool, int F) {
    int g = blockIdx.x;
    int beg = gptr[g], end = gptr[g + 1];
    float inv = 1.f / fmaxf((float)(end - beg), 1.f);
    for (int f = threadIdx.x; f < F; f += blockDim.x) {
        float s0 = 0.f, s1 = 0.f, s2 = 0.f, s3 = 0.f;
        int i = beg;
        for (; i + 3 < end; i += 4) {
            s0 += x[(size_t)(i + 0) * F + f];
            s1 += x[(size_t)(i + 1) * F + f];
            s2 += x[(size_t)(i + 2) * F + f];
            s3 += x[(size_t)(i + 3) * F + f];
        }
        for (; i < end; i++) s0 += x[(size_t)i * F + f];
        pool[(size_t)g * F + f] = (s0 + s1 + s2 + s3) * inv;
    }
}

// ---------------- SIMT SGEMM (templated tiles, double-buffered) ----------------
template <int MH, int NH>
__global__ __launch_bounds__(256) void k_sgemm(
    const float* __restrict__ A, const float* __restrict__ W,
    const float* __restrict__ bias, float* __restrict__ C,
    int N, int K, int M, int ldc, int relu)
{
    constexpr int TBM = 64 * MH;
    constexpr int TBN = 64 * NH;
    constexpr int CA = TBM / 32;
    constexpr int TPRA = 8 / CA;
    constexpr int CB = TBN / 32;

    __shared__ float As[2][8][TBM];
    __shared__ float Bs[2][8][TBN];

    int tid = threadIdx.x;
    int row0 = blockIdx.y * TBM;
    int col0 = blockIdx.x * TBN;
    int tx = tid & 15;
    int ty = tid >> 4;

    int a_r = tid / TPRA;
    int a_k = (tid % TPRA) * CA;
    int b_k = tid >> 5;
    int b_c = (tid & 31) * CB;

    int ar = row0 + a_r;
    const float* Arow = A + (size_t)(ar < N ? ar : 0) * K;
    bool a_ok = (ar < N);

    float acc[4 * MH][4 * NH];
#pragma unroll
    for (int i = 0; i < 4 * MH; i++)
#pragma unroll
        for (int j = 0; j < 4 * NH; j++) acc[i][j] = 0.f;

    float ra[CA], rb[CB];
    int kt = (K + 7) / 8;

#pragma unroll
    for (int i = 0; i < CA; i++) {
        int kc = a_k + i;
        ra[i] = (a_ok && kc < K) ? Arow[kc] : 0.f;
    }
#pragma unroll
    for (int i = 0; i < CB; i++) {
        int bc = col0 + b_c + i;
        rb[i] = (b_k < K && bc < M) ? W[(size_t)b_k * M + bc] : 0.f;
    }
#pragma unroll
    for (int i = 0; i < CA; i++) As[0][a_k + i][a_r] = ra[i];
#pragma unroll
    for (int i = 0; i < CB; i++) Bs[0][b_k][b_c + i] = rb[i];
    __syncthreads();

    int buf = 0;
    for (int t = 0; t < kt; t++) {
        int k_next = (t + 1) * 8;
        if (t + 1 < kt) {
#pragma unroll
            for (int i = 0; i < CA; i++) {
                int kc = k_next + a_k + i;
                ra[i] = (a_ok && kc < K) ? Arow[kc] : 0.f;
            }
            int bk = k_next + b_k;
#pragma unroll
            for (int i = 0; i < CB; i++) {
                int bc = col0 + b_c + i;
                rb[i] = (bk < K && bc < M) ? W[(size_t)bk * M + bc] : 0.f;
            }
        }

#pragma unroll
        for (int kk = 0; kk < 8; kk++) {
            float af[4 * MH], bf[4 * NH];
#pragma unroll
            for (int h = 0; h < MH; h++)
#pragma unroll
                for (int i = 0; i < 4; i++)
                    af[h * 4 + i] = As[buf][kk][h * 64 + ty * 4 + i];
#pragma unroll
            for (int h = 0; h < NH; h++)
#pragma unroll
                for (int j = 0; j < 4; j++)
                    bf[h * 4 + j] = Bs[buf][kk][h * 64 + tx * 4 + j];
#pragma unroll
            for (int i = 0; i < 4 * MH; i++)
#pragma unroll
                for (int j = 0; j < 4 * NH; j++) acc[i][j] += af[i] * bf[j];
        }

        if (t + 1 < kt) {
            int nb = buf ^ 1;
#pragma unroll
            for (int i = 0; i < CA; i++) As[nb][a_k + i][a_r] = ra[i];
#pragma unroll
            for (int i = 0; i < CB; i++) Bs[nb][b_k][b_c + i] = rb[i];
            __syncthreads();
            buf = nb;
        }
    }

#pragma unroll
    for (int hm = 0; hm < MH; hm++) {
#pragma unroll
        for (int i = 0; i < 4; i++) {
            int r = row0 + hm * 64 + ty * 4 + i;
            if (r >= N) continue;
#pragma unroll
            for (int hn = 0; hn < NH; hn++) {
#pragma unroll
                for (int j = 0; j < 4; j++) {
                    int c = col0 + hn * 64 + tx * 4 + j;
                    if (c >= M) continue;
                    float v = acc[hm * 4 + i][hn * 4 + j] + (bias ? bias[c] : 0.f);
                    if (relu) v = fmaxf(v, 0.f);
                    C[(size_t)r * ldc + c] = v;
                }
            }
        }
    }
}

static void launch_sgemm(const float* A, const float* W, const float* bias, float* C,
                         int N, int K, int M, int ldc, int relu, cudaStream_t st) {
    int best_bm = 128, best_bn = 128;
    double best_score = 1e30;
    for (int bm = 128; bm >= 64; bm -= 64) {
        for (int bn = 128; bn >= 64; bn -= 64) {
            double padw = (double)((long)gdiv(N, bm) * bm) * ((long)gdiv(M, bn) * bn);
            long ctas = (long)gdiv(N, bm) * gdiv(M, bn);
            double occ_pen = (ctas < 296) ? (296.0 / (double)ctas) : 1.0;
            double tile_pen = (bm == 64 ? 1.06 : 1.0) * (bn == 64 ? 1.06 : 1.0);
            double score = padw * occ_pen * tile_pen;
            if (score < best_score) { best_score = score; best_bm = bm; best_bn = bn; }
        }
    }
    dim3 grid(gdiv(M, best_bn), gdiv(N, best_bm));
    if (best_bm == 128 && best_bn == 128)      k_sgemm<2, 2><<<grid, 256, 0, st>>>(A, W, bias, C, N, K, M, ldc, relu);
    else if (best_bm == 128 && best_bn == 64)  k_sgemm<2, 1><<<grid, 256, 0, st>>>(A, W, bias, C, N, K, M, ldc, relu);
    else if (best_bm == 64 && best_bn == 128)  k_sgemm<1, 2><<<grid, 256, 0, st>>>(A, W, bias, C, N, K, M, ldc, relu);
    else                                       k_sgemm<1, 1><<<grid, 256, 0, st>>>(A, W, bias, C, N, K, M, ldc, relu);
}

// ---------------- branch orchestration (mol: SIMT everywhere) ----------------
static void run_branch_mol(const float* x0, const int* ei, int E, const int* bat, int N,
                           int F0, int F1, int F2, int F3,
                           const float* w1, const float* b1,
                           const float* w2, const float* b2,
                           const float* w3, const float* b3,
                           const float* fw1, const float* fb1,
                           const float* fw2, const float* fb2,
                           float* cat_ptr,
                           float* Y, float* A, float* Bf,
                           float* nrm, int* deg, int* cur, int* rowptr, int* csr,
                           int* bsum, int* gcnt, int* gptr, float* pool, float* fc1,
                           cudaStream_t st)
{
    const int* src = ei;
    const int* dst = ei + E;
    const int T = 256;
    int nb = gdiv(N, 1024);

    k_zero2i<<<gdiv(N, T), T, 0, st>>>(deg, cur, N);
    k_hist<<<gdiv(E, T), T, 0, st>>>(dst, deg, E);
    k_scan_blk<<<nb, 1024, 0, st>>>(deg, rowptr, bsum, N);
    launch_sgemm(x0, w1, nullptr, Y, N, F0, F1, F1, 0, st);
    k_scan_small<<<1, 128, 0, st>>>(bsum, nb);
    k_scan_add<<<gdiv(N, T), T, 0, st>>>(rowptr, bsum, N, nb);
    k_nrm<<<gdiv(N, T), T, 0, st>>>(deg, nrm, N);
    k_fill<<<gdiv(E, T), T, 0, st>>>(src, dst, rowptr, cur, csr, E);

    launch_agg(Y, nrm, rowptr, csr, A, N, F1, b1, 1, st);
    launch_agg(A, nrm, rowptr, csr, Y, N, F1, nullptr, 0, st);
    launch_sgemm(Y, w2, b2, Bf, N, F1, F2, F2, 1, st);
    launch_agg(Bf, nrm, rowptr, csr, Y, N, F2, nullptr, 0, st);
    launch_sgemm(Y, w3, b3, A, N, F2, F3, F3, 1, st);

    k_zeroi<<<1, 256, 0, st>>>(gcnt, 256);
    k_hist<<<gdiv(N, T), T, 0, st>>>(bat, gcnt, N);
    k_scan_ex<<<1, 1024, 0, st>>>(gcnt, gptr, 256);
    k_pool<<<256, 256, 0, st>>>(A, gptr, pool, F3);

    launch_sgemm(pool, fw1, fb1, fc1, 256, F3, 1024, 1024, 1, st);
    launch_sgemm(fc1, fw2, fb2, cat_ptr, 256, 1024, 128, 256, 0, st);
}

extern "C" void kernel_launch(void* const* d_in, const int* in_sizes, int n_in,
                              void* d_out, int out_size)
{
    static cudaStream_t s2 = nullptr;
    static cudaEvent_t evFork = nullptr, evJoin = nullptr;
    if (!s2) {
        cudaStreamCreateWithFlags(&s2, cudaStreamNonBlocking);
        cudaEventCreateWithFlags(&evFork, cudaEventDisableTiming);
        cudaEventCreateWithFlags(&evJoin, cudaEventDisableTiming);
        cudaFuncSetAttribute(k_wgemm, cudaFuncAttributeMaxDynamicSharedMemorySize, WG_SMEM);
    }

    float *Y, *A, *Bf, *nrm, *pool, *fc1;
    int *deg, *cur, *rowptr, *csr, *bsum, *gcnt, *gptr;
    float *mY, *mA, *mBf, *mnrm, *mpool, *mfc1;
    int *mdeg, *mcur, *mrowptr, *mcsr, *mbsum, *mgcnt, *mgptr;
    float *cat, *head;
    __nv_bfloat16 *Ab, *Wb2, *Wb3;
    cudaGetSymbolAddress((void**)&Y,       g_Y);
    cudaGetSymbolAddress((void**)&A,       g_A);
    cudaGetSymbolAddress((void**)&Bf,      g_B);
    cudaGetSymbolAddress((void**)&nrm,     g_nrm);
    cudaGetSymbolAddress((void**)&deg,     g_deg);
    cudaGetSymbolAddress((void**)&cur,     g_cur);
    cudaGetSymbolAddress((void**)&rowptr,  g_rowptr);
    cudaGetSymbolAddress((void**)&csr,     g_csr);
    cudaGetSymbolAddress((void**)&bsum,    g_bsum);
    cudaGetSymbolAddress((void**)&gcnt,    g_gcnt);
    cudaGetSymbolAddress((void**)&gptr,    g_gptr);
    cudaGetSymbolAddress((void**)&pool,    g_pool);
    cudaGetSymbolAddress((void**)&fc1,     g_fc1);
    cudaGetSymbolAddress((void**)&Ab,      g_Ab);
    cudaGetSymbolAddress((void**)&Wb2,     g_Wb2);
    cudaGetSymbolAddress((void**)&Wb3,     g_Wb3);
    cudaGetSymbolAddress((void**)&mY,      m_Y);
    cudaGetSymbolAddress((void**)&mA,      m_A);
    cudaGetSymbolAddress((void**)&mBf,     m_B);
    cudaGetSymbolAddress((void**)&mnrm,    m_nrm);
    cudaGetSymbolAddress((void**)&mdeg,    m_deg);
    cudaGetSymbolAddress((void**)&mcur,    m_cur);
    cudaGetSymbolAddress((void**)&mrowptr, m_rowptr);
    cudaGetSymbolAddress((void**)&mcsr,    m_csr);
    cudaGetSymbolAddress((void**)&mbsum,   m_bsum);
    cudaGetSymbolAddress((void**)&mgcnt,   m_gcnt);
    cudaGetSymbolAddress((void**)&mgptr,   m_gptr);
    cudaGetSymbolAddress((void**)&mpool,   m_pool);
    cudaGetSymbolAddress((void**)&mfc1,    m_fc1);
    cudaGetSymbolAddress((void**)&cat,     g_cat);
    cudaGetSymbolAddress((void**)&head,    g_head);

    const float* mol_x  = (const float*)d_in[0];
    const int*   mol_ei = (const int*)  d_in[1];
    const int*   mol_b  = (const int*)  d_in[2];
    const float* pro_x  = (const float*)d_in[3];
    const int*   pro_ei = (const int*)  d_in[4];
    const int*   pro_b  = (const int*)  d_in[5];

    int N_mol = in_sizes[2];
    int E_mol = in_sizes[1] / 2;
    int F_mol = in_sizes[0] / N_mol;     // 78
    int N_pro = in_sizes[5];
    int E_pro = in_sizes[4] / 2;
    int F_pro = in_sizes[3] / N_pro;     // 54

    const float* mw1  = (const float*)d_in[6];
    const float* mb1  = (const float*)d_in[7];
    const float* mw2  = (const float*)d_in[8];
    const float* mb2  = (const float*)d_in[9];
    const float* mw3  = (const float*)d_in[10];
    const float* mb3  = (const float*)d_in[11];
    const float* mfw1 = (const float*)d_in[12];
    const float* mfb1 = (const float*)d_in[13];
    const float* mfw2 = (const float*)d_in[14];
    const float* mfb2 = (const float*)d_in[15];
    const float* pw1  = (const float*)d_in[16];
    const float* pb1  = (const float*)d_in[17];
    const float* pw2  = (const float*)d_in[18];
    const float* pb2  = (const float*)d_in[19];
    const float* pw3  = (const float*)d_in[20];
    const float* pb3  = (const float*)d_in[21];
    const float* pfw1 = (const float*)d_in[22];
    const float* pfb1 = (const float*)d_in[23];
    const float* pfw2 = (const float*)d_in[24];
    const float* pfb2 = (const float*)d_in[25];
    const float* fc1w = (const float*)d_in[26];
    const float* fc1b = (const float*)d_in[27];
    const float* fc2w = (const float*)d_in[28];
    const float* fc2b = (const float*)d_in[29];
    const float* outw = (const float*)d_in[30];
    const float* outb = (const float*)d_in[31];

    // pro branch dims
    int F0 = F_pro, F1 = F_pro, F2 = 2 * F_pro, F3 = 4 * F_pro;  // 54,54,108,216
    int Kp2 = pad64(F1);     // 64
    int Mp2 = pad128i(F2);   // 128
    int Kp3 = pad64(F2);     // 128
    int Mp3 = pad128i(F3);   // 256

    // fork: mol branch on s2
    cudaEventRecord(evFork, 0);
    cudaStreamWaitEvent(s2, evFork, 0);

    run_branch_mol(mol_x, mol_ei, E_mol, mol_b, N_mol,
                   F_mol, F_mol, 2 * F_mol, 4 * F_mol,
                   mw1, mb1, mw2, mb2, mw3, mb3,
                   mfw1, mfb1, mfw2, mfb2,
                   cat,
                   mY, mA, mBf, mnrm, mdeg, mcur, mrowptr, mcsr,
                   mbsum, mgcnt, mgptr, mpool, mfc1, s2);

    // ---- protein branch on stream 0 (wmma for L2/L3) ----
    {
        const int* src = pro_ei;
        const int* dst = pro_ei + E_pro;
        const int T = 256;
        int N = N_pro;
        int nb = gdiv(N, 1024);

        // hoisted weight packs (input-independent)
        k_cvtWpack<<<gdiv(Mp2 * Kp2, 256), 256>>>(pw2, Wb2, F1, F2, Kp2, Mp2);
        k_cvtWpack<<<gdiv(Mp3 * Kp3, 256), 256>>>(pw3, Wb3, F2, F3, Kp3, Mp3);

        k_zero2i<<<gdiv(N, T), T>>>(deg, cur, N);
        k_hist<<<gdiv(E_pro, T), T>>>(dst, deg, E_pro);
        k_scan_blk<<<nb, 1024>>>(deg, rowptr, bsum, N);
        launch_sgemm(pro_x, pw1, nullptr, Y, N, F0, F1, F1, 0, 0);
        k_scan_small<<<1, 128>>>(bsum, nb);
        k_scan_add<<<gdiv(N, T), T>>>(rowptr, bsum, N, nb);
        k_nrm<<<gdiv(N, T), T>>>(deg, nrm, N);
        k_fill<<<gdiv(E_pro, T), T>>>(src, dst, rowptr, cur, csr, E_pro);

        // layer 1 epilogue
        launch_agg(Y, nrm, rowptr, csr, A, N, F1, pb1, 1, 0);

        // layer 2: split-bf16 agg -> wmma
        launch_aggb(A, nrm, rowptr, csr, Ab, N, F1, Kp2, 0);
        launch_wg(Ab, Wb2, pb2, Bf, N, Kp2, Mp2, F2, F2, 1, 0);

        // layer 3
        launch_aggb(Bf, nrm, rowptr, csr, Ab, N, F2, Kp3, 0);
        launch_wg(Ab, Wb3, pb3, A, N, Kp3, Mp3, F3, F3, 1, 0);

        // mean pool
        k_zeroi<<<1, 256>>>(gcnt, 256);
        k_hist<<<gdiv(N, T), T>>>(pro_b, gcnt, N);
        k_scan_ex<<<1, 1024>>>(gcnt, gptr, 256);
        k_pool<<<256, 256>>>(A, gptr, pool, F3);

        launch_sgemm(pool, pfw1, pfb1, fc1, 256, F3, 1024, 1024, 1, 0);
        launch_sgemm(fc1, pfw2, pfb2, cat + 128, 256, 1024, 128, 256, 0, 0);
    }

    // join
    cudaEventRecord(evJoin, s2);
    cudaStreamWaitEvent(0, evJoin, 0);

    // combined head
    launch_sgemm(cat,  fc1w, fc1b, fc1,           256, 256,  1024, 1024, 1, 0);
    launch_sgemm(fc1,  fc2w, fc2b, head,          256, 1024, 512,  512,  1, 0);
    launch_sgemm(head, outw, outb, (float*)d_out, 256, 512,  1,    1,    0, 0);
}